// round 1
// baseline (speedup 1.0000x reference)
#include <cuda_runtime.h>
#include <cuda_bf16.h>
#include <math.h>

#define BB 32
#define HID 2048
#define INNER 4096
#define NH 8
#define HEAD 512
#define K3 12288
#define CAP 30.0f
#define EPS 1e-6f
#define GN_EPS 1e-5f

// ---------------- scratch (device globals; no allocs allowed) ----------------
__device__ float g_xn  [BB * HID];
__device__ float g_xm  [BB * INNER];
__device__ float g_xg  [BB * INNER];
__device__ float g_xmc [BB * INNER];
__device__ float g_qkv [BB * K3];
__device__ float g_h   [BB * INNER];
__device__ float g_ig  [BB * NH];
__device__ float g_fg  [BB * NH];

// ---------------- output layout ----------------
// y:         [0,            65536)
// conv_new:  [65536,        458752)
// cell_new:  [458752,       67567616)
// norm_new:  [67567616,     67698688)
// max_new:   [67698688,     67698944)
#define Y_OFF    0
#define CONV_OFF 65536
#define CELL_OFF 458752
#define NORM_OFF 67567616
#define MAX_OFF  67698688

// ============================================================================
// 1) RMSNorm: xn = x * rsqrt(mean(x^2)+eps) * rms_w
// ============================================================================
__global__ void rmsnorm_kernel(const float* __restrict__ x,
                               const float* __restrict__ rms_w)
{
    __shared__ float red[256];
    int b = blockIdx.x;
    int tid = threadIdx.x;
    const float* xr = x + b * HID;
    float s = 0.f;
    #pragma unroll
    for (int i = tid; i < HID; i += 256) { float v = xr[i]; s += v * v; }
    red[tid] = s; __syncthreads();
    for (int st = 128; st > 0; st >>= 1) {
        if (tid < st) red[tid] += red[tid + st];
        __syncthreads();
    }
    float rstd = rsqrtf(red[0] / (float)HID + EPS);
    float* o = g_xn + b * HID;
    for (int i = tid; i < HID; i += 256) o[i] = xr[i] * rstd * rms_w[i];
}

// ============================================================================
// 2) Skinny GEMM: C[32,N] = A[32,K] @ W[N,K]^T  (+ optional addv[32,N])
//    BN=64, BK=64, 256 threads. Weight-streaming, float4 coalesced.
// ============================================================================
__global__ void gemm_skinny(const float* __restrict__ A,
                            const float* __restrict__ W,
                            float* __restrict__ C,
                            int N, int K,
                            const float* __restrict__ addv)
{
    __shared__ float As[64][33];      // [kk][m]
    __shared__ float Ws[64][65];      // [kk][n]
    const int n0 = blockIdx.x * 64;
    const int tid = threadIdx.x;
    const int tx = tid & 15;          // n quad
    const int ty = tid >> 4;          // m pair
    float acc[2][4] = {{0,0,0,0},{0,0,0,0}};

    for (int k0 = 0; k0 < K; k0 += 64) {
        // A tile: 32x64 = 512 float4, 2 per thread
        #pragma unroll
        for (int r = 0; r < 2; r++) {
            int id = tid + r * 256;
            int m = id >> 4;
            int c4 = id & 15;
            float4 v = *(const float4*)(A + (size_t)m * K + k0 + c4 * 4);
            As[c4*4+0][m] = v.x; As[c4*4+1][m] = v.y;
            As[c4*4+2][m] = v.z; As[c4*4+3][m] = v.w;
        }
        // W tile: 64x64 = 1024 float4, 4 per thread
        #pragma unroll
        for (int r = 0; r < 4; r++) {
            int id = tid + r * 256;
            int n = id >> 4;
            int c4 = id & 15;
            float4 v = *(const float4*)(W + (size_t)(n0 + n) * K + k0 + c4 * 4);
            Ws[c4*4+0][n] = v.x; Ws[c4*4+1][n] = v.y;
            Ws[c4*4+2][n] = v.z; Ws[c4*4+3][n] = v.w;
        }
        __syncthreads();
        #pragma unroll
        for (int kk = 0; kk < 64; kk++) {
            float a0 = As[kk][ty*2+0];
            float a1 = As[kk][ty*2+1];
            float w0 = Ws[kk][tx*4+0], w1 = Ws[kk][tx*4+1];
            float w2 = Ws[kk][tx*4+2], w3 = Ws[kk][tx*4+3];
            acc[0][0] += a0*w0; acc[0][1] += a0*w1; acc[0][2] += a0*w2; acc[0][3] += a0*w3;
            acc[1][0] += a1*w0; acc[1][1] += a1*w1; acc[1][2] += a1*w2; acc[1][3] += a1*w3;
        }
        __syncthreads();
    }
    #pragma unroll
    for (int r = 0; r < 2; r++) {
        int m = ty*2 + r;
        int n = n0 + tx*4;
        float4 v = make_float4(acc[r][0], acc[r][1], acc[r][2], acc[r][3]);
        if (addv) {
            float4 s = *(const float4*)(addv + (size_t)m * N + n);
            v.x += s.x; v.y += s.y; v.z += s.z; v.w += s.w;
        }
        *(float4*)(C + (size_t)m * N + n) = v;
    }
}

// ============================================================================
// 3) Conv + silu + new_conv_state
// ============================================================================
__global__ void conv_kernel(const float* __restrict__ conv_state,
                            const float* __restrict__ conv_w,
                            const float* __restrict__ conv_b,
                            float* __restrict__ out)
{
    int idx = blockIdx.x * blockDim.x + threadIdx.x;   // b*INNER + c
    if (idx >= BB * INNER) return;
    int c = idx & (INNER - 1);
    const float* cs = conv_state + (size_t)idx * 3;
    float s0 = cs[0], s1 = cs[1], s2 = cs[2];
    float xm = g_xm[idx];
    const float* w = conv_w + c * 4;
    float xc = s0*w[0] + s1*w[1] + s2*w[2] + xm*w[3] + conv_b[c];
    float* nc = out + CONV_OFF + (size_t)idx * 3;
    nc[0] = s1; nc[1] = s2; nc[2] = xm;
    g_xmc[idx] = xc / (1.f + expf(-xc));               // silu
}

// ============================================================================
// 4) Gates: ig/fg pre-acts (dot over 12288), tanh-cap, log-sigmoid, max_new
// ============================================================================
__global__ void gate_kernel(const float* __restrict__ Wi, const float* __restrict__ bi,
                            const float* __restrict__ Wf, const float* __restrict__ bf,
                            const float* __restrict__ max_state,
                            float* __restrict__ out)
{
    __shared__ float ri[256], rf[256];
    int bh = blockIdx.x;                 // b*NH + h
    int h = bh & (NH - 1);
    int b = bh >> 3;
    int tid = threadIdx.x;
    const float4* q4 = (const float4*)(g_qkv + (size_t)b * K3);
    const float4* wi4 = (const float4*)(Wi + (size_t)h * K3);
    const float4* wf4 = (const float4*)(Wf + (size_t)h * K3);
    float si = 0.f, sf = 0.f;
    #pragma unroll 4
    for (int j = tid; j < K3/4; j += 256) {
        float4 q = q4[j], a = wi4[j], f = wf4[j];
        si += q.x*a.x + q.y*a.y + q.z*a.z + q.w*a.w;
        sf += q.x*f.x + q.y*f.y + q.z*f.z + q.w*f.w;
    }
    ri[tid] = si; rf[tid] = sf; __syncthreads();
    for (int st = 128; st > 0; st >>= 1) {
        if (tid < st) { ri[tid] += ri[tid+st]; rf[tid] += rf[tid+st]; }
        __syncthreads();
    }
    if (tid == 0) {
        float ig = CAP * tanhf((ri[0] + bi[h]) / CAP);
        float fg = CAP * tanhf((rf[0] + bf[h]) / CAP);
        float lf = (fg >= 0.f) ? -log1pf(expf(-fg)) : (fg - log1pf(expf(fg)));
        float m_old = max_state[bh];
        float m_new = fmaxf(ig, m_old + lf);
        g_ig[bh] = expf(ig - m_new);
        g_fg[bh] = expf(lf + m_old - m_new);
        out[MAX_OFF + bh] = m_new;
    }
}

// ============================================================================
// 5) Cell update + numer + norm_new + qn + GroupNorm + gating -> h
//    One block per (b,h). 256 threads, each owns e-pair (2*tid, 2*tid+1).
// ============================================================================
__global__ void cell_kernel(const float* __restrict__ cell_state,
                            const float* __restrict__ norm_state,
                            const float* __restrict__ gn_w,
                            const float* __restrict__ gn_b,
                            const float* __restrict__ skip_w,
                            float* __restrict__ out)
{
    __shared__ float qs[HEAD], ks[HEAD], red[256];
    int bh = blockIdx.x;
    int h = bh & (NH - 1);
    int b = bh >> 3;
    int tid = threadIdx.x;

    const float KSCALE = 0.044194173824159216f;   // 1/sqrt(512)
    const float* qrow = g_qkv + (size_t)b * K3 + h * HEAD;
    const float* krow = qrow + INNER;
    const float* vrow = qrow + 2 * INNER;
    #pragma unroll
    for (int r = 0; r < 2; r++) {
        int e = tid + r * 256;
        qs[e] = qrow[e];
        ks[e] = krow[e] * KSCALE;
    }
    __syncthreads();

    float fg = g_fg[bh];
    float ig = g_ig[bh];
    float m_new = out[MAX_OFF + bh];

    int e0 = 2 * tid;
    float v0 = vrow[e0], v1 = vrow[e0 + 1];
    float iv0 = ig * v0, iv1 = ig * v1;

    const float* cin = cell_state + (size_t)bh * HEAD * HEAD;
    float* cout = out + CELL_OFF + (size_t)bh * HEAD * HEAD;

    float n0 = 0.f, n1 = 0.f;
    #pragma unroll 4
    for (int d = 0; d < HEAD; d++) {
        float2 cv = *(const float2*)(cin + (size_t)d * HEAD + e0);
        float kd = ks[d];
        float c0 = fg * cv.x + kd * iv0;
        float c1 = fg * cv.y + kd * iv1;
        *(float2*)(cout + (size_t)d * HEAD + e0) = make_float2(c0, c1);
        float qd = qs[d];
        n0 += qd * c0;
        n1 += qd * c1;
    }

    // norm_new + qn
    float qn_part = 0.f;
    #pragma unroll
    for (int r = 0; r < 2; r++) {
        int d = tid + r * 256;
        float nn = fg * norm_state[(size_t)bh * HEAD + d] + ig * ks[d];
        out[NORM_OFF + (size_t)bh * HEAD + d] = nn;
        qn_part += qs[d] * nn;
    }
    red[tid] = qn_part; __syncthreads();
    for (int st = 128; st > 0; st >>= 1) {
        if (tid < st) red[tid] += red[tid + st];
        __syncthreads();
    }
    float qn = red[0]; __syncthreads();
    float denom = fmaxf(fabsf(qn), expf(-m_new)) + EPS;

    float o0 = n0 / denom, o1 = n1 / denom;

    // mean
    red[tid] = o0 + o1; __syncthreads();
    for (int st = 128; st > 0; st >>= 1) {
        if (tid < st) red[tid] += red[tid + st];
        __syncthreads();
    }
    float mu = red[0] / (float)HEAD; __syncthreads();
    // var
    float d0 = o0 - mu, d1 = o1 - mu;
    red[tid] = d0*d0 + d1*d1; __syncthreads();
    for (int st = 128; st > 0; st >>= 1) {
        if (tid < st) red[tid] += red[tid + st];
        __syncthreads();
    }
    float rstd = rsqrtf(red[0] / (float)HEAD + GN_EPS);

    int c = h * HEAD + e0;
    size_t gidx = (size_t)b * INNER + c;
    #pragma unroll
    for (int j = 0; j < 2; j++) {
        float on = ((j ? d1 : d0)) * rstd;
        float og = on * gn_w[c + j] + gn_b[c + j];
        float xg = g_xg[gidx + j];
        float sg = xg / (1.f + expf(-xg));
        g_h[gidx + j] = (og + skip_w[c + j] * g_xmc[gidx + j]) * sg;
    }
}

// ============================================================================
extern "C" void kernel_launch(void* const* d_in, const int* in_sizes, int n_in,
                              void* d_out, int out_size)
{
    const float* x          = (const float*)d_in[0];
    const float* conv_state = (const float*)d_in[1];
    const float* cell_state = (const float*)d_in[2];
    const float* norm_state = (const float*)d_in[3];
    const float* max_state  = (const float*)d_in[4];
    const float* rms_w      = (const float*)d_in[5];
    const float* Wx         = (const float*)d_in[6];
    const float* Wg         = (const float*)d_in[7];
    const float* Wqkv       = (const float*)d_in[8];
    const float* conv_w     = (const float*)d_in[9];
    const float* conv_b     = (const float*)d_in[10];
    const float* Wi         = (const float*)d_in[11];
    const float* bi         = (const float*)d_in[12];
    const float* Wf         = (const float*)d_in[13];
    const float* bf         = (const float*)d_in[14];
    const float* gn_w       = (const float*)d_in[15];
    const float* gn_b       = (const float*)d_in[16];
    const float* Wdown      = (const float*)d_in[17];
    const float* skip_w     = (const float*)d_in[18];
    float* out = (float*)d_out;

    float* pxn;  cudaGetSymbolAddress((void**)&pxn,  g_xn);
    float* pxm;  cudaGetSymbolAddress((void**)&pxm,  g_xm);
    float* pxg;  cudaGetSymbolAddress((void**)&pxg,  g_xg);
    float* pxmc; cudaGetSymbolAddress((void**)&pxmc, g_xmc);
    float* pqkv; cudaGetSymbolAddress((void**)&pqkv, g_qkv);
    float* ph;   cudaGetSymbolAddress((void**)&ph,   g_h);

    // 1) rmsnorm
    rmsnorm_kernel<<<BB, 256>>>(x, rms_w);
    // 2) x_mlstm = xn @ Wx^T    (32x2048 @ 2048x4096)
    gemm_skinny<<<INNER/64, 256>>>(pxn, Wx, pxm, INNER, HID, nullptr);
    // 3) x_gate = xn @ Wg^T
    gemm_skinny<<<INNER/64, 256>>>(pxn, Wg, pxg, INNER, HID, nullptr);
    // 4) conv + silu + new_conv_state
    conv_kernel<<<(BB*INNER)/256, 256>>>(conv_state, conv_w, conv_b, out);
    // 5) qkv = xmc @ Wqkv^T   (32x4096 @ 4096x12288)
    gemm_skinny<<<K3/64, 256>>>(pxmc, Wqkv, pqkv, K3, INNER, nullptr);
    // 6) gates
    gate_kernel<<<BB*NH, 256>>>(Wi, bi, Wf, bf, max_state, out);
    // 7) cell update + groupnorm + gating -> h
    cell_kernel<<<BB*NH, 256>>>(cell_state, norm_state, gn_w, gn_b, skip_w, out);
    // 8) y = h @ Wdown^T + x
    gemm_skinny<<<HID/64, 256>>>(ph, Wdown, out + Y_OFF, HID, INNER, x);
}

// round 2
// speedup vs baseline: 2.2161x; 2.2161x over previous
#include <cuda_runtime.h>
#include <cuda_bf16.h>
#include <math.h>

#define BB 32
#define HID 2048
#define INNER 4096
#define NH 8
#define HEAD 512
#define K3 12288
#define CAP 30.0f
#define EPS 1e-6f
#define GN_EPS 1e-5f

// ---------------- scratch (device globals; no allocs allowed) ----------------
__device__ float g_xn  [BB * HID];
__device__ float g_xm  [BB * INNER];
__device__ float g_xg  [BB * INNER];
__device__ float g_xmc [BB * INNER];
__device__ float g_qkv [BB * K3];
__device__ float g_h   [BB * INNER];
__device__ float g_part[2 * BB * K3];   // split-K partials (max need: 2*32*12288)

// ---------------- output layout ----------------
#define Y_OFF    0
#define CONV_OFF 65536
#define CELL_OFF 458752
#define NORM_OFF 67567616
#define MAX_OFF  67698688

// ---------------- f32x2 packed FMA helpers ----------------
__device__ __forceinline__ void fma2(unsigned long long& d,
                                     unsigned long long a,
                                     unsigned long long b)
{
    asm("fma.rn.f32x2 %0, %1, %2, %0;" : "+l"(d) : "l"(a), "l"(b));
}
__device__ __forceinline__ unsigned long long dup2(float x)
{
    unsigned long long r;
    asm("mov.b64 %0, {%1, %1};" : "=l"(r) : "f"(x));
    return r;
}
union U64F2 { unsigned long long u; float2 f; };

// ============================================================================
// 1) RMSNorm
// ============================================================================
__global__ void rmsnorm_kernel(const float* __restrict__ x,
                               const float* __restrict__ rms_w)
{
    __shared__ float red[256];
    int b = blockIdx.x;
    int tid = threadIdx.x;
    const float* xr = x + b * HID;
    float s = 0.f;
    for (int i = tid; i < HID; i += 256) { float v = xr[i]; s += v * v; }
    red[tid] = s; __syncthreads();
    for (int st = 128; st > 0; st >>= 1) {
        if (tid < st) red[tid] += red[tid + st];
        __syncthreads();
    }
    float rstd = rsqrtf(red[0] / (float)HID + EPS);
    float* o = g_xn + b * HID;
    for (int i = tid; i < HID; i += 256) o[i] = xr[i] * rstd * rms_w[i];
}

// ============================================================================
// 2) Skinny GEMM with f32x2, double buffering, optional dual-W + split-K.
//    C[32,N] = A[32,K] @ W[N,K]^T  — BM=32, BN=64, BK=32, 256 threads.
//    Threads: kp = tid>>7 splits kk range; t=tid&127: tm=t>>3 (2 rows), tn=t&7 (8 cols).
//    blockIdx.y = k-split index; writes to C + by*32*N (caller sizes grid.y).
//    If blockIdx.x >= nb1: use W2/C2 (fused second GEMM, same N,K).
// ============================================================================
__global__ __launch_bounds__(256) void gemm_f32x2(
    const float* __restrict__ A,
    const float* __restrict__ W1, float* __restrict__ C1,
    const float* __restrict__ W2, float* __restrict__ C2,
    int nb1, int N, int Kt, int kLen)
{
    __shared__ float As[2][32][36];
    __shared__ float Ws[2][32][72];
    __shared__ float comb[128][17];

    const int bx = blockIdx.x;
    const float* W = (bx < nb1) ? W1 : W2;
    float* C = ((bx < nb1) ? C1 : C2) + (size_t)blockIdx.y * 32 * N;
    const int n0 = ((bx < nb1) ? bx : bx - nb1) * 64;
    const int kBeg = blockIdx.y * kLen;

    const int tid = threadIdx.x;
    const int kp = tid >> 7;
    const int t  = tid & 127;
    const int tn = t & 7;
    const int tm = t >> 3;

    // loader assignments
    const int lm  = tid >> 3;        // 0..31 (A row / W row-part)
    const int lc4 = tid & 7;         // 0..7  (k float4)
    const float* pA  = A + (size_t)lm * Kt + kBeg + lc4 * 4;
    const float* pW0 = W + (size_t)(n0 + lm) * Kt + kBeg + lc4 * 4;
    const float* pW1 = W + (size_t)(n0 + 32 + lm) * Kt + kBeg + lc4 * 4;

    unsigned long long acc[2][4];
    #pragma unroll
    for (int i = 0; i < 2; i++)
        #pragma unroll
        for (int j = 0; j < 4; j++) acc[i][j] = 0ull;

    const int T = kLen / 32;

    // preload tile 0
    {
        float4 va = *(const float4*)pA;
        float4 w0 = *(const float4*)pW0;
        float4 w1 = *(const float4*)pW1;
        As[0][lc4*4+0][lm] = va.x; As[0][lc4*4+1][lm] = va.y;
        As[0][lc4*4+2][lm] = va.z; As[0][lc4*4+3][lm] = va.w;
        Ws[0][lc4*4+0][lm] = w0.x; Ws[0][lc4*4+1][lm] = w0.y;
        Ws[0][lc4*4+2][lm] = w0.z; Ws[0][lc4*4+3][lm] = w0.w;
        Ws[0][lc4*4+0][32+lm] = w1.x; Ws[0][lc4*4+1][32+lm] = w1.y;
        Ws[0][lc4*4+2][32+lm] = w1.z; Ws[0][lc4*4+3][32+lm] = w1.w;
    }
    __syncthreads();

    for (int tile = 0; tile < T; tile++) {
        const int cur = tile & 1;
        const int nxt = cur ^ 1;
        float4 va, w0, w1;
        bool have_next = (tile + 1 < T);
        if (have_next) {
            const float* a = pA  + (tile + 1) * 32;
            const float* b = pW0 + (tile + 1) * 32;
            const float* c = pW1 + (tile + 1) * 32;
            va = *(const float4*)a;
            w0 = *(const float4*)b;
            w1 = *(const float4*)c;
        }

        #pragma unroll
        for (int kk = kp * 16; kk < kp * 16 + 16; kk++) {
            float2 a2 = *(const float2*)(&As[cur][kk][2 * tm]);
            unsigned long long a0 = dup2(a2.x), a1 = dup2(a2.y);
            ulonglong2 w01 = *(const ulonglong2*)(&Ws[cur][kk][8 * tn]);
            ulonglong2 w23 = *(const ulonglong2*)(&Ws[cur][kk][8 * tn + 4]);
            fma2(acc[0][0], a0, w01.x); fma2(acc[0][1], a0, w01.y);
            fma2(acc[0][2], a0, w23.x); fma2(acc[0][3], a0, w23.y);
            fma2(acc[1][0], a1, w01.x); fma2(acc[1][1], a1, w01.y);
            fma2(acc[1][2], a1, w23.x); fma2(acc[1][3], a1, w23.y);
        }

        if (have_next) {
            As[nxt][lc4*4+0][lm] = va.x; As[nxt][lc4*4+1][lm] = va.y;
            As[nxt][lc4*4+2][lm] = va.z; As[nxt][lc4*4+3][lm] = va.w;
            Ws[nxt][lc4*4+0][lm] = w0.x; Ws[nxt][lc4*4+1][lm] = w0.y;
            Ws[nxt][lc4*4+2][lm] = w0.z; Ws[nxt][lc4*4+3][lm] = w0.w;
            Ws[nxt][lc4*4+0][32+lm] = w1.x; Ws[nxt][lc4*4+1][32+lm] = w1.y;
            Ws[nxt][lc4*4+2][32+lm] = w1.z; Ws[nxt][lc4*4+3][32+lm] = w1.w;
        }
        __syncthreads();
    }

    // combine kp halves
    if (kp == 1) {
        #pragma unroll
        for (int i = 0; i < 2; i++)
            #pragma unroll
            for (int j = 0; j < 4; j++) {
                U64F2 u; u.u = acc[i][j];
                comb[t][i*8 + j*2]     = u.f.x;
                comb[t][i*8 + j*2 + 1] = u.f.y;
            }
    }
    __syncthreads();
    if (kp == 0) {
        #pragma unroll
        for (int i = 0; i < 2; i++) {
            float4 o0, o1;
            U64F2 u0, u1, u2, u3;
            u0.u = acc[i][0]; u1.u = acc[i][1]; u2.u = acc[i][2]; u3.u = acc[i][3];
            o0.x = u0.f.x + comb[t][i*8+0];
            o0.y = u0.f.y + comb[t][i*8+1];
            o0.z = u1.f.x + comb[t][i*8+2];
            o0.w = u1.f.y + comb[t][i*8+3];
            o1.x = u2.f.x + comb[t][i*8+4];
            o1.y = u2.f.y + comb[t][i*8+5];
            o1.z = u3.f.x + comb[t][i*8+6];
            o1.w = u3.f.y + comb[t][i*8+7];
            float* cr = C + (size_t)(2*tm + i) * N + n0 + 8*tn;
            *(float4*)(cr)     = o0;
            *(float4*)(cr + 4) = o1;
        }
    }
}

// ============================================================================
// 3) Split-K reduce: C = sum_s part[s] (+ addv)
// ============================================================================
__global__ void reduce_split(const float* __restrict__ part, int S, int elems,
                             const float* __restrict__ addv, float* __restrict__ C)
{
    int i = blockIdx.x * blockDim.x + threadIdx.x;   // float4 index
    const float4* p = (const float4*)part;
    int q = elems >> 2;
    float4 s = p[i];
    for (int j = 1; j < S; j++) {
        float4 t = p[i + (size_t)j * q];
        s.x += t.x; s.y += t.y; s.z += t.z; s.w += t.w;
    }
    if (addv) {
        float4 a = ((const float4*)addv)[i];
        s.x += a.x; s.y += a.y; s.z += a.z; s.w += a.w;
    }
    ((float4*)C)[i] = s;
}

// ============================================================================
// 4) Conv + silu + new_conv_state
// ============================================================================
__global__ void conv_kernel(const float* __restrict__ conv_state,
                            const float* __restrict__ conv_w,
                            const float* __restrict__ conv_b,
                            float* __restrict__ out)
{
    int idx = blockIdx.x * blockDim.x + threadIdx.x;
    if (idx >= BB * INNER) return;
    int c = idx & (INNER - 1);
    const float* cs = conv_state + (size_t)idx * 3;
    float s0 = cs[0], s1 = cs[1], s2 = cs[2];
    float xm = g_xm[idx];
    const float* w = conv_w + c * 4;
    float xc = s0*w[0] + s1*w[1] + s2*w[2] + xm*w[3] + conv_b[c];
    float* nc = out + CONV_OFF + (size_t)idx * 3;
    nc[0] = s1; nc[1] = s2; nc[2] = xm;
    g_xmc[idx] = xc / (1.f + expf(-xc));
}

// ============================================================================
// 5) Fused gates + cell update + numer + norm_new + qn + GroupNorm + h
//    One block per (b,h), 512 threads (4 row-groups x 128 col-threads, float4).
// ============================================================================
__global__ __launch_bounds__(512) void cell_kernel(
    const float* __restrict__ cell_state,
    const float* __restrict__ norm_state,
    const float* __restrict__ max_state,
    const float* __restrict__ Wi, const float* __restrict__ bi,
    const float* __restrict__ Wf, const float* __restrict__ bf,
    const float* __restrict__ gn_w, const float* __restrict__ gn_b,
    const float* __restrict__ skip_w,
    float* __restrict__ out)
{
    __shared__ float qs[HEAD], ks[HEAD];
    __shared__ float redA[512], redB[512];
    __shared__ float part[4][HEAD];
    __shared__ float s_ig, s_fg, s_mnew;

    const int bh = blockIdx.x;
    const int h = bh & (NH - 1);
    const int b = bh >> 3;
    const int tid = threadIdx.x;
    const float KSCALE = 0.044194173824159216f;   // 1/sqrt(512)

    const float* qkvrow = g_qkv + (size_t)b * K3;
    const float* qrow = qkvrow + h * HEAD;
    const float* krow = qrow + INNER;
    const float* vrow = qrow + 2 * INNER;

    // q/k into shared
    qs[tid] = qrow[tid];
    ks[tid] = krow[tid] * KSCALE;

    // gate dots: qkv . Wi[h], qkv . Wf[h]
    {
        const float4* q4  = (const float4*)qkvrow;
        const float4* wi4 = (const float4*)(Wi + (size_t)h * K3);
        const float4* wf4 = (const float4*)(Wf + (size_t)h * K3);
        float si = 0.f, sf = 0.f;
        #pragma unroll
        for (int r = 0; r < K3/4/512; r++) {
            int j = tid + r * 512;
            float4 q = q4[j], a = wi4[j], f = wf4[j];
            si += q.x*a.x + q.y*a.y + q.z*a.z + q.w*a.w;
            sf += q.x*f.x + q.y*f.y + q.z*f.z + q.w*f.w;
        }
        redA[tid] = si; redB[tid] = sf;
    }
    __syncthreads();
    for (int st = 256; st > 0; st >>= 1) {
        if (tid < st) { redA[tid] += redA[tid+st]; redB[tid] += redB[tid+st]; }
        __syncthreads();
    }
    if (tid == 0) {
        float ig = CAP * tanhf((redA[0] + bi[h]) / CAP);
        float fg = CAP * tanhf((redB[0] + bf[h]) / CAP);
        float lf = (fg >= 0.f) ? -log1pf(expf(-fg)) : (fg - log1pf(expf(fg)));
        float m_old = max_state[bh];
        float m_new = fmaxf(ig, m_old + lf);
        s_ig = expf(ig - m_new);
        s_fg = expf(lf + m_old - m_new);
        s_mnew = m_new;
        out[MAX_OFF + bh] = m_new;
    }
    __syncthreads();
    const float ig = s_ig, fg = s_fg, m_new = s_mnew;

    // main cell stream: 4 row-groups x 128 col-threads, float4 columns
    const int ct = tid & 127;
    const int rg = tid >> 7;
    const int e0 = ct * 4;
    float4 v = *(const float4*)(vrow + e0);
    float4 iv = make_float4(ig*v.x, ig*v.y, ig*v.z, ig*v.w);

    const float* cin  = cell_state + (size_t)bh * HEAD * HEAD;
    float*       cout = out + CELL_OFF + (size_t)bh * HEAD * HEAD;

    float4 nacc = make_float4(0.f, 0.f, 0.f, 0.f);
    const int d0 = rg * 128;
    #pragma unroll 4
    for (int d = d0; d < d0 + 128; d++) {
        float4 cv = *(const float4*)(cin + (size_t)d * HEAD + e0);
        float kd = ks[d];
        float4 c;
        c.x = fmaf(fg, cv.x, kd * iv.x);
        c.y = fmaf(fg, cv.y, kd * iv.y);
        c.z = fmaf(fg, cv.z, kd * iv.z);
        c.w = fmaf(fg, cv.w, kd * iv.w);
        *(float4*)(cout + (size_t)d * HEAD + e0) = c;
        float qd = qs[d];
        nacc.x = fmaf(qd, c.x, nacc.x);
        nacc.y = fmaf(qd, c.y, nacc.y);
        nacc.z = fmaf(qd, c.z, nacc.z);
        nacc.w = fmaf(qd, c.w, nacc.w);
    }
    ((float4*)&part[rg][0])[ct] = nacc;
    __syncthreads();

    // per-column epilogue: col = tid
    float num = part[0][tid] + part[1][tid] + part[2][tid] + part[3][tid];
    float nn = fmaf(fg, norm_state[(size_t)bh * HEAD + tid], ig * ks[tid]);
    out[NORM_OFF + (size_t)bh * HEAD + tid] = nn;

    redA[tid] = qs[tid] * nn;
    __syncthreads();
    for (int st = 256; st > 0; st >>= 1) {
        if (tid < st) redA[tid] += redA[tid+st];
        __syncthreads();
    }
    float qn = redA[0]; __syncthreads();
    float denom = fmaxf(fabsf(qn), expf(-m_new)) + EPS;
    float o = num / denom;

    redA[tid] = o; __syncthreads();
    for (int st = 256; st > 0; st >>= 1) {
        if (tid < st) redA[tid] += redA[tid+st];
        __syncthreads();
    }
    float mu = redA[0] / (float)HEAD; __syncthreads();
    float dv = o - mu;
    redA[tid] = dv * dv; __syncthreads();
    for (int st = 256; st > 0; st >>= 1) {
        if (tid < st) redA[tid] += redA[tid+st];
        __syncthreads();
    }
    float rstd = rsqrtf(redA[0] / (float)HEAD + GN_EPS);

    int c = h * HEAD + tid;
    size_t gidx = (size_t)b * INNER + c;
    float og = fmaf(dv * rstd, gn_w[c], gn_b[c]);
    float xg = g_xg[gidx];
    float sg = xg / (1.f + expf(-xg));
    g_h[gidx] = (og + skip_w[c] * g_xmc[gidx]) * sg;
}

// ============================================================================
extern "C" void kernel_launch(void* const* d_in, const int* in_sizes, int n_in,
                              void* d_out, int out_size)
{
    const float* x          = (const float*)d_in[0];
    const float* conv_state = (const float*)d_in[1];
    const float* cell_state = (const float*)d_in[2];
    const float* norm_state = (const float*)d_in[3];
    const float* max_state  = (const float*)d_in[4];
    const float* rms_w      = (const float*)d_in[5];
    const float* Wx         = (const float*)d_in[6];
    const float* Wg         = (const float*)d_in[7];
    const float* Wqkv       = (const float*)d_in[8];
    const float* conv_w     = (const float*)d_in[9];
    const float* conv_b     = (const float*)d_in[10];
    const float* Wi         = (const float*)d_in[11];
    const float* bi         = (const float*)d_in[12];
    const float* Wf         = (const float*)d_in[13];
    const float* bf         = (const float*)d_in[14];
    const float* gn_w       = (const float*)d_in[15];
    const float* gn_b       = (const float*)d_in[16];
    const float* Wdown      = (const float*)d_in[17];
    const float* skip_w     = (const float*)d_in[18];
    float* out = (float*)d_out;

    float* pxn;   cudaGetSymbolAddress((void**)&pxn,   g_xn);
    float* pxm;   cudaGetSymbolAddress((void**)&pxm,   g_xm);
    float* pxg;   cudaGetSymbolAddress((void**)&pxg,   g_xg);
    float* pxmc;  cudaGetSymbolAddress((void**)&pxmc,  g_xmc);
    float* pqkv;  cudaGetSymbolAddress((void**)&pqkv,  g_qkv);
    float* ph;    cudaGetSymbolAddress((void**)&ph,    g_h);
    float* ppart; cudaGetSymbolAddress((void**)&ppart, g_part);

    // 1) rmsnorm
    rmsnorm_kernel<<<BB, 256>>>(x, rms_w);
    // 2) x_mlstm & x_gate fused: 128 blocks
    gemm_f32x2<<<dim3(128, 1), 256>>>(pxn, Wx, pxm, Wg, pxg, 64, INNER, HID, HID);
    // 3) conv + silu + new_conv_state
    conv_kernel<<<(BB*INNER)/256, 256>>>(conv_state, conv_w, conv_b, out);
    // 4) qkv = xmc @ Wqkv^T, split-K 2 -> partials
    gemm_f32x2<<<dim3(K3/64, 2), 256>>>(pxmc, Wqkv, ppart, nullptr, nullptr,
                                        K3/64, K3, INNER, INNER/2);
    // 5) reduce partials -> qkv
    reduce_split<<<(BB*K3/4)/256, 256>>>(ppart, 2, BB*K3, nullptr, pqkv);
    // 6) fused gates + cell update + groupnorm + gating -> h   (ncu -s 5 slot)
    cell_kernel<<<BB*NH, 512>>>(cell_state, norm_state, max_state,
                                Wi, bi, Wf, bf, gn_w, gn_b, skip_w, out);
    // 7) y partials = h @ Wdown^T, split-K 4
    gemm_f32x2<<<dim3(HID/64, 4), 256>>>(ph, Wdown, ppart, nullptr, nullptr,
                                         HID/64, HID, INNER, INNER/4);
    // 8) reduce partials + skip -> y
    reduce_split<<<(BB*HID/4)/256, 256>>>(ppart, 4, BB*HID, x, out + Y_OFF);
}

// round 3
// speedup vs baseline: 3.8400x; 1.7328x over previous
#include <cuda_runtime.h>
#include <cuda_bf16.h>
#include <math.h>

#define BB 32
#define HID 2048
#define INNER 4096
#define NH 8
#define HEAD 512
#define K3 12288
#define CAP 30.0f
#define EPS 1e-6f
#define GN_EPS 1e-5f

// ---------------- scratch (device globals; no allocs allowed) ----------------
__device__ float g_xn  [BB * HID];
__device__ float g_xm  [BB * INNER];
__device__ float g_xg  [BB * INNER];
__device__ float g_xmc [BB * INNER];
__device__ float g_qkv [BB * K3];
__device__ float g_h   [BB * INNER];
__device__ float g_part[16 * BB * K3];   // split-K partials (max: 16*32*12288)

// ---------------- output layout ----------------
#define Y_OFF    0
#define CONV_OFF 65536
#define CELL_OFF 458752
#define NORM_OFF 67567616
#define MAX_OFF  67698688

// ---------------- helpers ----------------
__device__ __forceinline__ void fma2(unsigned long long& d,
                                     unsigned long long a,
                                     unsigned long long b)
{
    asm("fma.rn.f32x2 %0, %1, %2, %0;" : "+l"(d) : "l"(a), "l"(b));
}
union U64F2 { unsigned long long u; float2 f; };

__device__ __forceinline__ void cp16(void* smem, const void* g)
{
    unsigned s = (unsigned)__cvta_generic_to_shared(smem);
    asm volatile("cp.async.cg.shared.global [%0], [%1], 16;\n" :: "r"(s), "l"(g));
}

// ============================================================================
// 1) RMSNorm
// ============================================================================
__global__ void rmsnorm_kernel(const float* __restrict__ x,
                               const float* __restrict__ rms_w)
{
    __shared__ float red[256];
    int b = blockIdx.x;
    int tid = threadIdx.x;
    const float* xr = x + b * HID;
    float s = 0.f;
    for (int i = tid; i < HID; i += 256) { float v = xr[i]; s += v * v; }
    red[tid] = s; __syncthreads();
    for (int st = 128; st > 0; st >>= 1) {
        if (tid < st) red[tid] += red[tid + st];
        __syncthreads();
    }
    float rstd = rsqrtf(red[0] / (float)HID + EPS);
    float* o = g_xn + b * HID;
    for (int i = tid; i < HID; i += 256) o[i] = xr[i] * rstd * rms_w[i];
}

// ============================================================================
// 2) GEMM v2: C[32,N] = A[32,K] @ W[N,K]^T, split-K partials.
//    BM=32, BN=256, BK=16, 256 threads, thread tile 8m x 4n.
//    k-major smem tiles filled by cp.async (no transpose, no STS).
//    fma2 = 2-wide k-dot. A reads = warp broadcast. W reads conflict-free.
//    Dual-W: blocks [0,nb1) use W1/C1, rest use W2/C2.
// ============================================================================
__global__ __launch_bounds__(256, 2) void gemm_v2(
    const float* __restrict__ A,
    const float* __restrict__ W1, float* __restrict__ C1,
    const float* __restrict__ W2, float* __restrict__ C2,
    int nb1, int N, int Kt, int kLen)
{
    __shared__ __align__(16) float As[2][32][20];
    __shared__ __align__(16) float Ws[2][256][20];

    const int bx = blockIdx.x;
    const float* W = (bx < nb1) ? W1 : W2;
    float* C = ((bx < nb1) ? C1 : C2) + (size_t)blockIdx.y * 32 * N;
    const int n0 = ((bx < nb1) ? bx : bx - nb1) * 256;
    const int kBeg = blockIdx.y * kLen;
    const int T = kLen >> 4;

    const int t = threadIdx.x;
    const int tn = t & 63;
    const int tm = t >> 6;

    const float* wsrc = W + (size_t)(n0 + t) * Kt + kBeg;
    const float* asrc = A + (size_t)(t >> 2) * Kt + kBeg + (t & 3) * 4;

    unsigned long long acc[8][4];
    #pragma unroll
    for (int i = 0; i < 8; i++)
        #pragma unroll
        for (int j = 0; j < 4; j++) acc[i][j] = 0ull;

    // prologue: tile 0
    {
        #pragma unroll
        for (int k4 = 0; k4 < 4; k4++)
            cp16(&Ws[0][t][k4*4], wsrc + k4*4);
        if (t < 128)
            cp16(&As[0][t>>2][(t&3)*4], asrc);
        asm volatile("cp.async.commit_group;\n");
    }

    for (int tile = 0; tile < T; tile++) {
        const int cur = tile & 1;
        const int nxt = cur ^ 1;
        if (tile + 1 < T) {
            const float* ws = wsrc + (tile + 1) * 16;
            #pragma unroll
            for (int k4 = 0; k4 < 4; k4++)
                cp16(&Ws[nxt][t][k4*4], ws + k4*4);
            if (t < 128)
                cp16(&As[nxt][t>>2][(t&3)*4], asrc + (tile + 1) * 16);
            asm volatile("cp.async.commit_group;\n");
            asm volatile("cp.async.wait_group 1;\n");
        } else {
            asm volatile("cp.async.wait_group 0;\n");
        }
        __syncthreads();

        #pragma unroll
        for (int k4 = 0; k4 < 4; k4++) {
            ulonglong2 a[8];
            #pragma unroll
            for (int i = 0; i < 8; i++)
                a[i] = *(const ulonglong2*)&As[cur][tm*8 + i][k4*4];
            #pragma unroll
            for (int j = 0; j < 4; j++) {
                ulonglong2 w = *(const ulonglong2*)&Ws[cur][j*64 + tn][k4*4];
                #pragma unroll
                for (int i = 0; i < 8; i++) {
                    fma2(acc[i][j], a[i].x, w.x);
                    fma2(acc[i][j], a[i].y, w.y);
                }
            }
        }
        __syncthreads();
    }

    // epilogue: horizontal add of the 2-wide dot, scalar coalesced stores
    #pragma unroll
    for (int i = 0; i < 8; i++) {
        float* cr = C + (size_t)(tm*8 + i) * N + n0;
        #pragma unroll
        for (int j = 0; j < 4; j++) {
            U64F2 u; u.u = acc[i][j];
            cr[j*64 + tn] = u.f.x + u.f.y;
        }
    }
}

// ============================================================================
// 3) Split-K reduce: C = sum_s part[s] (+ addv)
// ============================================================================
__global__ void reduce_split(const float* __restrict__ part, int S, int elems,
                             const float* __restrict__ addv, float* __restrict__ C)
{
    int i = blockIdx.x * blockDim.x + threadIdx.x;   // float4 index
    const float4* p = (const float4*)part;
    int q = elems >> 2;
    float4 s = p[i];
    for (int j = 1; j < S; j++) {
        float4 t = p[i + (size_t)j * q];
        s.x += t.x; s.y += t.y; s.z += t.z; s.w += t.w;
    }
    if (addv) {
        float4 a = ((const float4*)addv)[i];
        s.x += a.x; s.y += a.y; s.z += a.z; s.w += a.w;
    }
    ((float4*)C)[i] = s;
}

// ============================================================================
// 4) Conv + silu + new_conv_state
// ============================================================================
__global__ void conv_kernel(const float* __restrict__ conv_state,
                            const float* __restrict__ conv_w,
                            const float* __restrict__ conv_b,
                            float* __restrict__ out)
{
    int idx = blockIdx.x * blockDim.x + threadIdx.x;
    if (idx >= BB * INNER) return;
    int c = idx & (INNER - 1);
    const float* cs = conv_state + (size_t)idx * 3;
    float s0 = cs[0], s1 = cs[1], s2 = cs[2];
    float xm = g_xm[idx];
    const float* w = conv_w + c * 4;
    float xc = s0*w[0] + s1*w[1] + s2*w[2] + xm*w[3] + conv_b[c];
    float* nc = out + CONV_OFF + (size_t)idx * 3;
    nc[0] = s1; nc[1] = s2; nc[2] = xm;
    g_xmc[idx] = xc / (1.f + expf(-xc));
}

// ============================================================================
// 5) Fused gates + cell update + numer + norm_new + qn + GroupNorm + h
// ============================================================================
__global__ __launch_bounds__(512) void cell_kernel(
    const float* __restrict__ cell_state,
    const float* __restrict__ norm_state,
    const float* __restrict__ max_state,
    const float* __restrict__ Wi, const float* __restrict__ bi,
    const float* __restrict__ Wf, const float* __restrict__ bf,
    const float* __restrict__ gn_w, const float* __restrict__ gn_b,
    const float* __restrict__ skip_w,
    float* __restrict__ out)
{
    __shared__ float qs[HEAD], ks[HEAD];
    __shared__ float redA[512], redB[512];
    __shared__ float part[4][HEAD];
    __shared__ float s_ig, s_fg, s_mnew;

    const int bh = blockIdx.x;
    const int h = bh & (NH - 1);
    const int b = bh >> 3;
    const int tid = threadIdx.x;
    const float KSCALE = 0.044194173824159216f;   // 1/sqrt(512)

    const float* qkvrow = g_qkv + (size_t)b * K3;
    const float* qrow = qkvrow + h * HEAD;
    const float* krow = qrow + INNER;
    const float* vrow = qrow + 2 * INNER;

    qs[tid] = qrow[tid];
    ks[tid] = krow[tid] * KSCALE;

    {
        const float4* q4  = (const float4*)qkvrow;
        const float4* wi4 = (const float4*)(Wi + (size_t)h * K3);
        const float4* wf4 = (const float4*)(Wf + (size_t)h * K3);
        float si = 0.f, sf = 0.f;
        #pragma unroll
        for (int r = 0; r < K3/4/512; r++) {
            int j = tid + r * 512;
            float4 q = q4[j], a = wi4[j], f = wf4[j];
            si += q.x*a.x + q.y*a.y + q.z*a.z + q.w*a.w;
            sf += q.x*f.x + q.y*f.y + q.z*f.z + q.w*f.w;
        }
        redA[tid] = si; redB[tid] = sf;
    }
    __syncthreads();
    for (int st = 256; st > 0; st >>= 1) {
        if (tid < st) { redA[tid] += redA[tid+st]; redB[tid] += redB[tid+st]; }
        __syncthreads();
    }
    if (tid == 0) {
        float ig = CAP * tanhf((redA[0] + bi[h]) / CAP);
        float fg = CAP * tanhf((redB[0] + bf[h]) / CAP);
        float lf = (fg >= 0.f) ? -log1pf(expf(-fg)) : (fg - log1pf(expf(fg)));
        float m_old = max_state[bh];
        float m_new = fmaxf(ig, m_old + lf);
        s_ig = expf(ig - m_new);
        s_fg = expf(lf + m_old - m_new);
        s_mnew = m_new;
        out[MAX_OFF + bh] = m_new;
    }
    __syncthreads();
    const float ig = s_ig, fg = s_fg, m_new = s_mnew;

    const int ct = tid & 127;
    const int rg = tid >> 7;
    const int e0 = ct * 4;
    float4 v = *(const float4*)(vrow + e0);
    float4 iv = make_float4(ig*v.x, ig*v.y, ig*v.z, ig*v.w);

    const float* cin  = cell_state + (size_t)bh * HEAD * HEAD;
    float*       cout = out + CELL_OFF + (size_t)bh * HEAD * HEAD;

    float4 nacc = make_float4(0.f, 0.f, 0.f, 0.f);
    const int d0 = rg * 128;
    #pragma unroll 4
    for (int d = d0; d < d0 + 128; d++) {
        float4 cv = *(const float4*)(cin + (size_t)d * HEAD + e0);
        float kd = ks[d];
        float4 c;
        c.x = fmaf(fg, cv.x, kd * iv.x);
        c.y = fmaf(fg, cv.y, kd * iv.y);
        c.z = fmaf(fg, cv.z, kd * iv.z);
        c.w = fmaf(fg, cv.w, kd * iv.w);
        *(float4*)(cout + (size_t)d * HEAD + e0) = c;
        float qd = qs[d];
        nacc.x = fmaf(qd, c.x, nacc.x);
        nacc.y = fmaf(qd, c.y, nacc.y);
        nacc.z = fmaf(qd, c.z, nacc.z);
        nacc.w = fmaf(qd, c.w, nacc.w);
    }
    ((float4*)&part[rg][0])[ct] = nacc;
    __syncthreads();

    float num = part[0][tid] + part[1][tid] + part[2][tid] + part[3][tid];
    float nn = fmaf(fg, norm_state[(size_t)bh * HEAD + tid], ig * ks[tid]);
    out[NORM_OFF + (size_t)bh * HEAD + tid] = nn;

    redA[tid] = qs[tid] * nn;
    __syncthreads();
    for (int st = 256; st > 0; st >>= 1) {
        if (tid < st) redA[tid] += redA[tid+st];
        __syncthreads();
    }
    float qn = redA[0]; __syncthreads();
    float denom = fmaxf(fabsf(qn), expf(-m_new)) + EPS;
    float o = num / denom;

    redA[tid] = o; __syncthreads();
    for (int st = 256; st > 0; st >>= 1) {
        if (tid < st) redA[tid] += redA[tid+st];
        __syncthreads();
    }
    float mu = redA[0] / (float)HEAD; __syncthreads();
    float dv = o - mu;
    redA[tid] = dv * dv; __syncthreads();
    for (int st = 256; st > 0; st >>= 1) {
        if (tid < st) redA[tid] += redA[tid+st];
        __syncthreads();
    }
    float rstd = rsqrtf(redA[0] / (float)HEAD + GN_EPS);

    int c = h * HEAD + tid;
    size_t gidx = (size_t)b * INNER + c;
    float og = fmaf(dv * rstd, gn_w[c], gn_b[c]);
    float xg = g_xg[gidx];
    float sg = xg / (1.f + expf(-xg));
    g_h[gidx] = (og + skip_w[c] * g_xmc[gidx]) * sg;
}

// ============================================================================
extern "C" void kernel_launch(void* const* d_in, const int* in_sizes, int n_in,
                              void* d_out, int out_size)
{
    const float* x          = (const float*)d_in[0];
    const float* conv_state = (const float*)d_in[1];
    const float* cell_state = (const float*)d_in[2];
    const float* norm_state = (const float*)d_in[3];
    const float* max_state  = (const float*)d_in[4];
    const float* rms_w      = (const float*)d_in[5];
    const float* Wx         = (const float*)d_in[6];
    const float* Wg         = (const float*)d_in[7];
    const float* Wqkv       = (const float*)d_in[8];
    const float* conv_w     = (const float*)d_in[9];
    const float* conv_b     = (const float*)d_in[10];
    const float* Wi         = (const float*)d_in[11];
    const float* bi         = (const float*)d_in[12];
    const float* Wf         = (const float*)d_in[13];
    const float* bf         = (const float*)d_in[14];
    const float* gn_w       = (const float*)d_in[15];
    const float* gn_b       = (const float*)d_in[16];
    const float* Wdown      = (const float*)d_in[17];
    const float* skip_w     = (const float*)d_in[18];
    float* out = (float*)d_out;

    float* pxn;   cudaGetSymbolAddress((void**)&pxn,   g_xn);
    float* pxm;   cudaGetSymbolAddress((void**)&pxm,   g_xm);
    float* pxg;   cudaGetSymbolAddress((void**)&pxg,   g_xg);
    float* pxmc;  cudaGetSymbolAddress((void**)&pxmc,  g_xmc);
    float* pqkv;  cudaGetSymbolAddress((void**)&pqkv,  g_qkv);
    float* ph;    cudaGetSymbolAddress((void**)&ph,    g_h);
    float* ppart; cudaGetSymbolAddress((void**)&ppart, g_part);

    float* pp2 = ppart + (size_t)8 * 32 * 4096;   // C2 partial base for Wx/Wg

    // 1) rmsnorm
    rmsnorm_kernel<<<BB, 256>>>(x, rms_w);

    // 2) x_mlstm & x_gate fused, split-K 8: grid (16+16, 8) = 256 blocks
    gemm_v2<<<dim3(32, 8), 256>>>(pxn, Wx, ppart, Wg, pp2, 16, INNER, HID, HID/8);
    reduce_split<<<(BB*INNER/4)/256, 256>>>(ppart, 8, BB*INNER, nullptr, pxm);
    reduce_split<<<(BB*INNER/4)/256, 256>>>(pp2,   8, BB*INNER, nullptr, pxg);

    // 3) conv + silu + new_conv_state
    conv_kernel<<<(BB*INNER)/256, 256>>>(conv_state, conv_w, conv_b, out);

    // 4) qkv = xmc @ Wqkv^T, split-K 16: grid (48, 16) = 768 blocks
    gemm_v2<<<dim3(48, 16), 256>>>(pxmc, Wqkv, ppart, nullptr, nullptr,
                                   48, K3, INNER, INNER/16);
    reduce_split<<<(BB*K3/4)/256, 256>>>(ppart, 16, BB*K3, nullptr, pqkv);

    // 5) fused gates + cell update + groupnorm + gating -> h
    cell_kernel<<<BB*NH, 512>>>(cell_state, norm_state, max_state,
                                Wi, bi, Wf, bf, gn_w, gn_b, skip_w, out);

    // 6) y = h @ Wdown^T + x, split-K 32: grid (8, 32) = 256 blocks
    gemm_v2<<<dim3(8, 32), 256>>>(ph, Wdown, ppart, nullptr, nullptr,
                                  8, HID, INNER, INNER/32);
    reduce_split<<<(BB*HID/4)/256, 256>>>(ppart, 32, BB*HID, x, out + Y_OFF);
}

// round 4
// speedup vs baseline: 4.0277x; 1.0489x over previous
#include <cuda_runtime.h>
#include <cuda_bf16.h>
#include <math.h>

#define BB 32
#define HID 2048
#define INNER 4096
#define NH 8
#define HEAD 512
#define K3 12288
#define CAP 30.0f
#define EPS 1e-6f
#define GN_EPS 1e-5f
#define KSCALE 0.044194173824159216f   // 1/sqrt(512)

// ---------------- scratch (device globals; no allocs allowed) ----------------
__device__ float g_xn   [BB * HID];
__device__ float g_xg   [BB * INNER];
__device__ float g_xmc  [BB * INNER];
__device__ float g_qkv  [BB * K3];
__device__ float g_h    [BB * INNER];
__device__ float g_part [16 * BB * K3];            // split-K partials
__device__ float g_numer[BB * NH * 4 * HEAD];      // cell numer partials
__device__ float g_ig   [BB * NH];
__device__ float g_fg   [BB * NH];

// ---------------- output layout ----------------
#define Y_OFF    0
#define CONV_OFF 65536
#define CELL_OFF 458752
#define NORM_OFF 67567616
#define MAX_OFF  67698688

// ---------------- helpers ----------------
__device__ __forceinline__ void fma2(unsigned long long& d,
                                     unsigned long long a,
                                     unsigned long long b)
{
    asm("fma.rn.f32x2 %0, %1, %2, %0;" : "+l"(d) : "l"(a), "l"(b));
}
union U64F2 { unsigned long long u; float2 f; };

__device__ __forceinline__ void cp16(void* smem, const void* g)
{
    unsigned s = (unsigned)__cvta_generic_to_shared(smem);
    asm volatile("cp.async.cg.shared.global [%0], [%1], 16;\n" :: "r"(s), "l"(g));
}

// ============================================================================
// 1) RMSNorm
// ============================================================================
__global__ void rmsnorm_kernel(const float* __restrict__ x,
                               const float* __restrict__ rms_w)
{
    __shared__ float red[256];
    int b = blockIdx.x;
    int tid = threadIdx.x;
    const float* xr = x + b * HID;
    float s = 0.f;
    for (int i = tid; i < HID; i += 256) { float v = xr[i]; s += v * v; }
    red[tid] = s; __syncthreads();
    for (int st = 128; st > 0; st >>= 1) {
        if (tid < st) red[tid] += red[tid + st];
        __syncthreads();
    }
    float rstd = rsqrtf(red[0] / (float)HID + EPS);
    float* o = g_xn + b * HID;
    for (int i = tid; i < HID; i += 256) o[i] = xr[i] * rstd * rms_w[i];
}

// ============================================================================
// 2) GEMM: C[32,N] = A[32,K] @ W[N,K]^T, uneven split-K partials.
//    BM=32, BN=256, BK=16, 256 threads, thread tile 8m x 4n, fma2 k-dots,
//    cp.async k-major tiles (no transpose). Dual-W via nb1.
// ============================================================================
__global__ __launch_bounds__(256, 2) void gemm_v2(
    const float* __restrict__ A,
    const float* __restrict__ W1, float* __restrict__ C1,
    const float* __restrict__ W2, float* __restrict__ C2,
    int nb1, int N, int Kt)
{
    __shared__ __align__(16) float As[2][32][20];
    __shared__ __align__(16) float Ws[2][256][20];

    const int bx = blockIdx.x;
    const float* W = (bx < nb1) ? W1 : W2;
    float* C = ((bx < nb1) ? C1 : C2) + (size_t)blockIdx.y * 32 * N;
    const int n0 = ((bx < nb1) ? bx : bx - nb1) * 256;

    // uneven k-split over 16-wide tiles
    const int TT = Kt >> 4;
    const int G = gridDim.y;
    const int base = TT / G;
    const int rem = TT - base * G;
    const int by = blockIdx.y;
    const int tBeg = by * base + (by < rem ? by : rem);
    const int T = base + (by < rem ? 1 : 0);
    const int kBeg = tBeg << 4;

    const int t = threadIdx.x;
    const int tn = t & 63;
    const int tm = t >> 6;

    const float* wsrc = W + (size_t)(n0 + t) * Kt + kBeg;
    const float* asrc = A + (size_t)(t >> 2) * Kt + kBeg + (t & 3) * 4;

    unsigned long long acc[8][4];
    #pragma unroll
    for (int i = 0; i < 8; i++)
        #pragma unroll
        for (int j = 0; j < 4; j++) acc[i][j] = 0ull;

    {
        #pragma unroll
        for (int k4 = 0; k4 < 4; k4++)
            cp16(&Ws[0][t][k4*4], wsrc + k4*4);
        if (t < 128)
            cp16(&As[0][t>>2][(t&3)*4], asrc);
        asm volatile("cp.async.commit_group;\n");
    }

    for (int tile = 0; tile < T; tile++) {
        const int cur = tile & 1;
        const int nxt = cur ^ 1;
        if (tile + 1 < T) {
            const float* ws = wsrc + (tile + 1) * 16;
            #pragma unroll
            for (int k4 = 0; k4 < 4; k4++)
                cp16(&Ws[nxt][t][k4*4], ws + k4*4);
            if (t < 128)
                cp16(&As[nxt][t>>2][(t&3)*4], asrc + (tile + 1) * 16);
            asm volatile("cp.async.commit_group;\n");
            asm volatile("cp.async.wait_group 1;\n");
        } else {
            asm volatile("cp.async.wait_group 0;\n");
        }
        __syncthreads();

        #pragma unroll
        for (int k4 = 0; k4 < 4; k4++) {
            ulonglong2 a[8];
            #pragma unroll
            for (int i = 0; i < 8; i++)
                a[i] = *(const ulonglong2*)&As[cur][tm*8 + i][k4*4];
            #pragma unroll
            for (int j = 0; j < 4; j++) {
                ulonglong2 w = *(const ulonglong2*)&Ws[cur][j*64 + tn][k4*4];
                #pragma unroll
                for (int i = 0; i < 8; i++) {
                    fma2(acc[i][j], a[i].x, w.x);
                    fma2(acc[i][j], a[i].y, w.y);
                }
            }
        }
        __syncthreads();
    }

    #pragma unroll
    for (int i = 0; i < 8; i++) {
        float* cr = C + (size_t)(tm*8 + i) * N + n0;
        #pragma unroll
        for (int j = 0; j < 4; j++) {
            U64F2 u; u.u = acc[i][j];
            cr[j*64 + tn] = u.f.x + u.f.y;
        }
    }
}

// ============================================================================
// 3) Templated split-K reduce: C = sum_s part[s] (+ addv)
// ============================================================================
template<int S>
__global__ void reduce_split_t(const float* __restrict__ part, int elems,
                               const float* __restrict__ addv,
                               float* __restrict__ C)
{
    int i = blockIdx.x * blockDim.x + threadIdx.x;
    const float4* p = (const float4*)part;
    int q = elems >> 2;
    float4 s = p[i];
    #pragma unroll
    for (int j = 1; j < S; j++) {
        float4 t = p[i + (size_t)j * q];
        s.x += t.x; s.y += t.y; s.z += t.z; s.w += t.w;
    }
    if (addv) {
        float4 a = ((const float4*)addv)[i];
        s.x += a.x; s.y += a.y; s.z += a.z; s.w += a.w;
    }
    ((float4*)C)[i] = s;
}

// ============================================================================
// 4) Conv + fused xm split-reduce + silu + new_conv_state
// ============================================================================
__global__ void conv_kernel(const float* __restrict__ conv_state,
                            const float* __restrict__ conv_w,
                            const float* __restrict__ conv_b,
                            const float* __restrict__ xm_part,
                            float* __restrict__ out)
{
    int idx = blockIdx.x * blockDim.x + threadIdx.x;
    if (idx >= BB * INNER) return;
    int c = idx & (INNER - 1);
    float xm = 0.f;
    #pragma unroll
    for (int s = 0; s < 8; s++) xm += xm_part[(size_t)s * BB * INNER + idx];
    const float* cs = conv_state + (size_t)idx * 3;
    float s0 = cs[0], s1 = cs[1], s2 = cs[2];
    const float* w = conv_w + c * 4;
    float xc = s0*w[0] + s1*w[1] + s2*w[2] + xm*w[3] + conv_b[c];
    float* nc = out + CONV_OFF + (size_t)idx * 3;
    nc[0] = s1; nc[1] = s2; nc[2] = xm;
    g_xmc[idx] = xc / (1.f + expf(-xc));
}

// ============================================================================
// 5) Gates: per (b,h) dot of qkv with Wi/Wf rows + stabilized exp factors
// ============================================================================
__global__ __launch_bounds__(256) void gate_kernel(
    const float* __restrict__ Wi, const float* __restrict__ bi,
    const float* __restrict__ Wf, const float* __restrict__ bf,
    const float* __restrict__ max_state,
    float* __restrict__ out)
{
    __shared__ float ri[256], rf[256];
    int bh = blockIdx.x;
    int h = bh & (NH - 1);
    int b = bh >> 3;
    int tid = threadIdx.x;
    const float4* q4  = (const float4*)(g_qkv + (size_t)b * K3);
    const float4* wi4 = (const float4*)(Wi + (size_t)h * K3);
    const float4* wf4 = (const float4*)(Wf + (size_t)h * K3);
    float si = 0.f, sf = 0.f;
    #pragma unroll
    for (int r = 0; r < K3/4/256; r++) {
        int j = tid + r * 256;
        float4 q = q4[j], a = wi4[j], f = wf4[j];
        si += q.x*a.x + q.y*a.y + q.z*a.z + q.w*a.w;
        sf += q.x*f.x + q.y*f.y + q.z*f.z + q.w*f.w;
    }
    ri[tid] = si; rf[tid] = sf; __syncthreads();
    for (int st = 128; st > 0; st >>= 1) {
        if (tid < st) { ri[tid] += ri[tid+st]; rf[tid] += rf[tid+st]; }
        __syncthreads();
    }
    if (tid == 0) {
        float ig = CAP * tanhf((ri[0] + bi[h]) / CAP);
        float fg = CAP * tanhf((rf[0] + bf[h]) / CAP);
        float lf = (fg >= 0.f) ? -log1pf(expf(-fg)) : (fg - log1pf(expf(fg)));
        float m_old = max_state[bh];
        float m_new = fmaxf(ig, m_old + lf);
        g_ig[bh] = expf(ig - m_new);
        g_fg[bh] = expf(lf + m_old - m_new);
        out[MAX_OFF + bh] = m_new;
    }
}

// ============================================================================
// 6) Cell stream: grid = 4 chunks x 256 bh; 256 threads.
//    Updates cell_new for a 128-row chunk and writes numer partials.
// ============================================================================
__global__ __launch_bounds__(256) void cell_stream(
    const float* __restrict__ cell_state,
    float* __restrict__ out)
{
    __shared__ float qsm[128], ksm[128];
    __shared__ float part[2][HEAD];

    const int bid = blockIdx.x;
    const int bh = bid >> 2;
    const int ch = bid & 3;
    const int h = bh & (NH - 1);
    const int b = bh >> 3;
    const int tid = threadIdx.x;

    const float* qrow = g_qkv + (size_t)b * K3 + h * HEAD;
    const float* krow = qrow + INNER;
    const float* vrow = qrow + 2 * INNER;
    const int d0 = ch * 128;

    if (tid < 128) {
        qsm[tid] = qrow[d0 + tid];
        ksm[tid] = krow[d0 + tid] * KSCALE;
    }
    __syncthreads();

    const float ig = g_ig[bh];
    const float fg = g_fg[bh];

    const int ct = tid & 127;
    const int rg = tid >> 7;
    const int e0 = ct * 4;
    float4 v = *(const float4*)(vrow + e0);
    float4 iv = make_float4(ig*v.x, ig*v.y, ig*v.z, ig*v.w);

    const float* cin  = cell_state + (size_t)bh * HEAD * HEAD;
    float*       cout = out + CELL_OFF + (size_t)bh * HEAD * HEAD;

    float4 nacc = make_float4(0.f, 0.f, 0.f, 0.f);
    #pragma unroll 4
    for (int dd = rg; dd < 128; dd += 2) {
        int d = d0 + dd;
        float4 cv = *(const float4*)(cin + (size_t)d * HEAD + e0);
        float kd = ksm[dd];
        float4 c;
        c.x = fmaf(fg, cv.x, kd * iv.x);
        c.y = fmaf(fg, cv.y, kd * iv.y);
        c.z = fmaf(fg, cv.z, kd * iv.z);
        c.w = fmaf(fg, cv.w, kd * iv.w);
        *(float4*)(cout + (size_t)d * HEAD + e0) = c;
        float qd = qsm[dd];
        nacc.x = fmaf(qd, c.x, nacc.x);
        nacc.y = fmaf(qd, c.y, nacc.y);
        nacc.z = fmaf(qd, c.z, nacc.z);
        nacc.w = fmaf(qd, c.w, nacc.w);
    }
    *(float4*)&part[rg][e0] = nacc;
    __syncthreads();
    if (tid < 128) {
        float4 p0 = *(const float4*)&part[0][e0];
        float4 p1 = *(const float4*)&part[1][e0];
        float4 s = make_float4(p0.x+p1.x, p0.y+p1.y, p0.z+p1.z, p0.w+p1.w);
        *(float4*)(g_numer + (size_t)bid * HEAD + e0) = s;
    }
}

// ============================================================================
// 7) Cell epilogue: norm_new + qn + denom + GroupNorm + gating -> h
// ============================================================================
__global__ __launch_bounds__(512) void cell_epi(
    const float* __restrict__ norm_state,
    const float* __restrict__ gn_w, const float* __restrict__ gn_b,
    const float* __restrict__ skip_w,
    float* __restrict__ out)
{
    __shared__ float red[512];
    const int bh = blockIdx.x;
    const int h = bh & (NH - 1);
    const int b = bh >> 3;
    const int tid = threadIdx.x;

    const float* qrow = g_qkv + (size_t)b * K3 + h * HEAD;
    const float* krow = qrow + INNER;
    float q = qrow[tid];
    float k = krow[tid] * KSCALE;

    const float ig = g_ig[bh];
    const float fg = g_fg[bh];
    const float m_new = out[MAX_OFF + bh];

    float num = g_numer[(size_t)(bh*4+0) * HEAD + tid]
              + g_numer[(size_t)(bh*4+1) * HEAD + tid]
              + g_numer[(size_t)(bh*4+2) * HEAD + tid]
              + g_numer[(size_t)(bh*4+3) * HEAD + tid];

    float nn = fmaf(fg, norm_state[(size_t)bh * HEAD + tid], ig * k);
    out[NORM_OFF + (size_t)bh * HEAD + tid] = nn;

    red[tid] = q * nn; __syncthreads();
    for (int st = 256; st > 0; st >>= 1) {
        if (tid < st) red[tid] += red[tid+st];
        __syncthreads();
    }
    float qn = red[0]; __syncthreads();
    float denom = fmaxf(fabsf(qn), expf(-m_new)) + EPS;
    float o = num / denom;

    red[tid] = o; __syncthreads();
    for (int st = 256; st > 0; st >>= 1) {
        if (tid < st) red[tid] += red[tid+st];
        __syncthreads();
    }
    float mu = red[0] / (float)HEAD; __syncthreads();
    float dv = o - mu;
    red[tid] = dv * dv; __syncthreads();
    for (int st = 256; st > 0; st >>= 1) {
        if (tid < st) red[tid] += red[tid+st];
        __syncthreads();
    }
    float rstd = rsqrtf(red[0] / (float)HEAD + GN_EPS);

    int c = h * HEAD + tid;
    size_t gidx = (size_t)b * INNER + c;
    float og = fmaf(dv * rstd, gn_w[c], gn_b[c]);
    float xg = g_xg[gidx];
    float sg = xg / (1.f + expf(-xg));
    g_h[gidx] = (og + skip_w[c] * g_xmc[gidx]) * sg;
}

// ============================================================================
extern "C" void kernel_launch(void* const* d_in, const int* in_sizes, int n_in,
                              void* d_out, int out_size)
{
    const float* x          = (const float*)d_in[0];
    const float* conv_state = (const float*)d_in[1];
    const float* cell_state = (const float*)d_in[2];
    const float* norm_state = (const float*)d_in[3];
    const float* max_state  = (const float*)d_in[4];
    const float* rms_w      = (const float*)d_in[5];
    const float* Wx         = (const float*)d_in[6];
    const float* Wg         = (const float*)d_in[7];
    const float* Wqkv       = (const float*)d_in[8];
    const float* conv_w     = (const float*)d_in[9];
    const float* conv_b     = (const float*)d_in[10];
    const float* Wi         = (const float*)d_in[11];
    const float* bi         = (const float*)d_in[12];
    const float* Wf         = (const float*)d_in[13];
    const float* bf         = (const float*)d_in[14];
    const float* gn_w       = (const float*)d_in[15];
    const float* gn_b       = (const float*)d_in[16];
    const float* Wdown      = (const float*)d_in[17];
    const float* skip_w     = (const float*)d_in[18];
    float* out = (float*)d_out;

    float* pxn;   cudaGetSymbolAddress((void**)&pxn,   g_xn);
    float* pxg;   cudaGetSymbolAddress((void**)&pxg,   g_xg);
    float* pxmc;  cudaGetSymbolAddress((void**)&pxmc,  g_xmc);
    float* pqkv;  cudaGetSymbolAddress((void**)&pqkv,  g_qkv);
    float* ph;    cudaGetSymbolAddress((void**)&ph,    g_h);
    float* ppart; cudaGetSymbolAddress((void**)&ppart, g_part);

    float* pp2 = ppart + (size_t)8 * BB * INNER;   // Wg partial base

    // 1) rmsnorm
    rmsnorm_kernel<<<BB, 256>>>(x, rms_w);

    // 2) x_mlstm & x_gate fused, split-K 8: grid (16+16, 8) = 256 blocks
    gemm_v2<<<dim3(32, 8), 256>>>(pxn, Wx, ppart, Wg, pp2, 16, INNER, HID);
    reduce_split_t<8><<<(BB*INNER/4)/256, 256>>>(pp2, BB*INNER, nullptr, pxg);

    // 3) conv + fused xm reduce + silu + new_conv_state
    conv_kernel<<<(BB*INNER)/256, 256>>>(conv_state, conv_w, conv_b, ppart, out);

    // 4) qkv = xmc @ Wqkv^T, uneven split-K 6: grid (48, 6) = 288 blocks
    gemm_v2<<<dim3(48, 6), 256>>>(pxmc, Wqkv, ppart, nullptr, nullptr,
                                  48, K3, INNER);
    reduce_split_t<6><<<(BB*K3/4)/256, 256>>>(ppart, BB*K3, nullptr, pqkv);

    // 5) gates
    gate_kernel<<<BB*NH, 256>>>(Wi, bi, Wf, bf, max_state, out);

    // 6) cell stream: 1024 blocks, one wave
    cell_stream<<<BB*NH*4, 256>>>(cell_state, out);

    // 7) cell epilogue -> h
    cell_epi<<<BB*NH, 512>>>(norm_state, gn_w, gn_b, skip_w, out);

    // 8) y = h @ Wdown^T + x, split-K 32: grid (8, 32) = 256 blocks
    gemm_v2<<<dim3(8, 32), 256>>>(ph, Wdown, ppart, nullptr, nullptr,
                                  8, HID, INNER);
    reduce_split_t<32><<<(BB*HID/4)/256, 256>>>(ppart, BB*HID, x, out + Y_OFF);
}